// round 1
// baseline (speedup 1.0000x reference)
#include <cuda_runtime.h>
#include <math.h>
#include <stdint.h>

// Problem constants (B=1)
#define H_   8
#define S_   1024
#define D_   64
#define KG_  10

// Tiling
#define BI   64
#define BJ   64
#define NT   256
#define NTILES (S_ / BJ)

// LUT
#define LUTN    4096
#define RANGE_D 10.0f
#define RANGE_E 5.0f

// smem strides (padded)
#define QSTR 68   // transposed Q/K tiles: [D][BI+4]
#define PSTR 68   // P tile: [BI][BJ+4]

__device__ float2 g_lutD[LUTN];
__device__ float2 g_lutE[LUTN];

// ---------------------------------------------------------------------------
// LUT construction: full RBF -> MLP(exact GELU) bias, evaluated on a grid.
// ---------------------------------------------------------------------------
__device__ __forceinline__ float gelu_exact(float x) {
    return 0.5f * x * (1.0f + erff(x * 0.70710678118654752f));
}

__device__ float bias_eval(float x,
                           const float* __restrict__ mu, const float* __restrict__ sg,
                           const float* __restrict__ bb,
                           const float* __restrict__ W1, const float* __restrict__ b1,
                           const float* __restrict__ W2, float b2v) {
    float psi[KG_];
#pragma unroll
    for (int k = 0; k < KG_; k++) {
        float s = sg[k];
        float z = (x + bb[k] - mu[k]) / s;
        psi[k] = expf(-0.5f * z * z) * (0.3989422804014327f / s);
    }
    float acc = b2v;
#pragma unroll
    for (int l = 0; l < KG_; l++) {
        float hv = b1[l];
#pragma unroll
        for (int k = 0; k < KG_; k++) hv = fmaf(W1[l * KG_ + k], psi[k], hv);
        acc = fmaf(W2[l], gelu_exact(hv), acc);
    }
    return acc;
}

__global__ void build_luts_kernel(const float* __restrict__ muD, const float* __restrict__ sgD,
                                  const float* __restrict__ bD,
                                  const float* __restrict__ muE, const float* __restrict__ sgE,
                                  const float* __restrict__ bE,
                                  const float* __restrict__ W1, const float* __restrict__ b1,
                                  const float* __restrict__ W2, const float* __restrict__ b2) {
    int i = blockIdx.x * blockDim.x + threadIdx.x;
    if (i >= LUTN) return;
    float b2v = b2[0];

    float hD = RANGE_D / (float)LUTN;
    float v0 = bias_eval((float)i * hD, muD, sgD, bD, W1, b1, W2, b2v);
    float v1 = bias_eval((float)(i + 1) * hD, muD, sgD, bD, W1, b1, W2, b2v);
    g_lutD[i] = make_float2(v0, v1 - v0);

    float hE = RANGE_E / (float)LUTN;
    v0 = bias_eval((float)i * hE, muE, sgE, bE, W1, b1, W2, b2v);
    v1 = bias_eval((float)(i + 1) * hE, muE, sgE, bE, W1, b1, W2, b2v);
    g_lutE[i] = make_float2(v0, v1 - v0);
}

// ---------------------------------------------------------------------------
// Fused flash attention with LUT biases.
// grid = (S/BI, H), block = 256 threads (16x16 thread grid, 4x4 micro-tile).
// ---------------------------------------------------------------------------
__device__ __forceinline__ float lut_interp(const float2* __restrict__ lut, float x, float scale) {
    float t = x * scale;
    int ix = (int)t;
    ix = max(0, min(ix, LUTN - 1));
    float f = t - (float)ix;
    float2 e = lut[ix];
    return fmaf(e.y, f, e.x);
}

__global__ __launch_bounds__(NT) void attn_kernel(
    const float* __restrict__ Qg, const float* __restrict__ Kg, const float* __restrict__ Vg,
    const float* __restrict__ DMg, const float* __restrict__ EMg, const int* __restrict__ Mg,
    float* __restrict__ Og) {
    extern __shared__ unsigned char smraw[];
    float2* lutD = (float2*)smraw;
    float2* lutE = lutD + LUTN;
    float* Qs = (float*)(lutE + LUTN);   // [D][QSTR] transposed
    float* Ks = Qs + D_ * QSTR;          // [D][QSTR] transposed
    float* Vs = Ks + D_ * QSTR;          // [BJ][D]
    float* Ps = Vs + BJ * D_;            // [BI][PSTR]

    const int tid = threadIdx.x;
    const int h = blockIdx.y;
    const int i0 = blockIdx.x * BI;
    const int tr = tid >> 4;   // 0..15: query-row group
    const int tc = tid & 15;   // 0..15: col group

    const float lscaleD = (float)LUTN / RANGE_D;
    const float lscaleE = (float)LUTN / RANGE_E;

    // Stage LUTs into shared (coalesced)
    for (int t = tid; t < LUTN; t += NT) lutD[t] = g_lutD[t];
    for (int t = tid; t < LUTN; t += NT) lutE[t] = g_lutE[t];

    // Load Q tile transposed: Qs[d][i]
    const float* Qbase = Qg + ((size_t)h * S_ + i0) * D_;
#pragma unroll
    for (int k = 0; k < (BI * D_ / 4) / NT; k++) {
        int fi = tid + k * NT;          // 0..1023
        int row = fi >> 4;              // 16 float4 per row
        int dcol = (fi & 15) * 4;
        float4 q = *(const float4*)(Qbase + row * D_ + dcol);
        Qs[(dcol + 0) * QSTR + row] = q.x;
        Qs[(dcol + 1) * QSTR + row] = q.y;
        Qs[(dcol + 2) * QSTR + row] = q.z;
        Qs[(dcol + 3) * QSTR + row] = q.w;
    }

    float o[4][4];
    float mrow[4], lrow[4];
#pragma unroll
    for (int r = 0; r < 4; r++) {
        mrow[r] = -1e30f;
        lrow[r] = 0.f;
#pragma unroll
        for (int c = 0; c < 4; c++) o[r][c] = 0.f;
    }

    const float qk_scale = 0.0883883476483184f;  // 1/sqrt(2*D)

    for (int jt = 0; jt < NTILES; jt++) {
        const int j0 = jt * BJ;
        __syncthreads();  // prev-iter P/K/V consumers done

        // Load K tile transposed: Ks[d][j]
        const float* Kbase = Kg + ((size_t)h * S_ + j0) * D_;
#pragma unroll
        for (int k = 0; k < 4; k++) {
            int fi = tid + k * NT;
            int row = fi >> 4;
            int dcol = (fi & 15) * 4;
            float4 v = *(const float4*)(Kbase + row * D_ + dcol);
            Ks[(dcol + 0) * QSTR + row] = v.x;
            Ks[(dcol + 1) * QSTR + row] = v.y;
            Ks[(dcol + 2) * QSTR + row] = v.z;
            Ks[(dcol + 3) * QSTR + row] = v.w;
        }
        // Load V tile straight: Vs[j][d]
        const float* Vbase = Vg + ((size_t)h * S_ + j0) * D_;
#pragma unroll
        for (int k = 0; k < 4; k++) {
            int fi = tid + k * NT;
            *(float4*)(Vs + fi * 4) = *(const float4*)(Vbase + fi * 4);
        }

        // Issue global loads for bias matrices + mask (latency hidden under QK)
        float4 dm[4], em[4];
        int4 mk[4];
#pragma unroll
        for (int r = 0; r < 4; r++) {
            int ig = i0 + tr * 4 + r;
            size_t base = ((size_t)h * S_ + ig) * S_ + j0 + tc * 4;
            dm[r] = *(const float4*)(DMg + base);
            em[r] = *(const float4*)(EMg + base);
            mk[r] = *(const int4*)(Mg + base);
        }

        __syncthreads();  // tiles visible

        // QK^T: 4x4 micro-tile per thread
        float sc[4][4];
#pragma unroll
        for (int r = 0; r < 4; r++)
#pragma unroll
            for (int c = 0; c < 4; c++) sc[r][c] = 0.f;

#pragma unroll 8
        for (int k = 0; k < D_; k++) {
            float4 a = *(const float4*)(Qs + k * QSTR + tr * 4);
            float4 b = *(const float4*)(Ks + k * QSTR + tc * 4);
            float av[4] = {a.x, a.y, a.z, a.w};
            float bv[4] = {b.x, b.y, b.z, b.w};
#pragma unroll
            for (int r = 0; r < 4; r++)
#pragma unroll
                for (int c = 0; c < 4; c++) sc[r][c] = fmaf(av[r], bv[c], sc[r][c]);
        }

        // scale + LUT biases + mask
#pragma unroll
        for (int r = 0; r < 4; r++) {
            const float* dp = (const float*)&dm[r];
            const float* ep = (const float*)&em[r];
            const int* mp = (const int*)&mk[r];
#pragma unroll
            for (int c = 0; c < 4; c++) {
                float s = sc[r][c] * qk_scale
                        + lut_interp(lutD, dp[c], lscaleD)
                        + lut_interp(lutE, ep[c], lscaleE);
                sc[r][c] = (mp[c] == 0) ? -1e9f : s;
            }
        }

        // Online softmax over this tile (row reduce across 16 lanes)
#pragma unroll
        for (int r = 0; r < 4; r++) {
            float mx = fmaxf(fmaxf(sc[r][0], sc[r][1]), fmaxf(sc[r][2], sc[r][3]));
            mx = fmaxf(mx, __shfl_xor_sync(0xffffffffu, mx, 8));
            mx = fmaxf(mx, __shfl_xor_sync(0xffffffffu, mx, 4));
            mx = fmaxf(mx, __shfl_xor_sync(0xffffffffu, mx, 2));
            mx = fmaxf(mx, __shfl_xor_sync(0xffffffffu, mx, 1));
            float mnew = fmaxf(mrow[r], mx);
            float corr = __expf(mrow[r] - mnew);
            mrow[r] = mnew;
            float ps = 0.f;
#pragma unroll
            for (int c = 0; c < 4; c++) {
                float p = __expf(sc[r][c] - mnew);
                sc[r][c] = p;
                ps += p;
            }
            ps += __shfl_xor_sync(0xffffffffu, ps, 8);
            ps += __shfl_xor_sync(0xffffffffu, ps, 4);
            ps += __shfl_xor_sync(0xffffffffu, ps, 2);
            ps += __shfl_xor_sync(0xffffffffu, ps, 1);
            lrow[r] = lrow[r] * corr + ps;
#pragma unroll
            for (int c = 0; c < 4; c++) o[r][c] *= corr;
            // Stage P tile (float4, padded stride)
            *(float4*)(Ps + (tr * 4 + r) * PSTR + tc * 4) =
                make_float4(sc[r][0], sc[r][1], sc[r][2], sc[r][3]);
        }

        __syncthreads();  // P + V visible

        // O += P * V
#pragma unroll 4
        for (int j = 0; j < BJ; j++) {
            float4 v = *(const float4*)(Vs + j * D_ + tc * 4);
            float vv[4] = {v.x, v.y, v.z, v.w};
            float pv[4];
#pragma unroll
            for (int r = 0; r < 4; r++) pv[r] = Ps[(tr * 4 + r) * PSTR + j];
#pragma unroll
            for (int r = 0; r < 4; r++)
#pragma unroll
                for (int c = 0; c < 4; c++) o[r][c] = fmaf(pv[r], vv[c], o[r][c]);
        }
    }

    // Epilogue: normalize + store
#pragma unroll
    for (int r = 0; r < 4; r++) {
        int ig = i0 + tr * 4 + r;
        float inv = 1.0f / lrow[r];
        float4 res = make_float4(o[r][0] * inv, o[r][1] * inv, o[r][2] * inv, o[r][3] * inv);
        *(float4*)(Og + ((size_t)h * S_ + ig) * D_ + tc * 4) = res;
    }
}

// ---------------------------------------------------------------------------
// kernel_launch
// Input order: Q, K, V, distance_matrix, energy_matrix, mask,
//              mu_D, sigma_D, b_D, mu_E, sigma_E, b_E, W1, b1, W2, b2
// ---------------------------------------------------------------------------
extern "C" void kernel_launch(void* const* d_in, const int* in_sizes, int n_in,
                              void* d_out, int out_size) {
    const float* Q  = (const float*)d_in[0];
    const float* K  = (const float*)d_in[1];
    const float* V  = (const float*)d_in[2];
    const float* DM = (const float*)d_in[3];
    const float* EM = (const float*)d_in[4];
    const int*   MK = (const int*)d_in[5];
    const float* muD = (const float*)d_in[6];
    const float* sgD = (const float*)d_in[7];
    const float* bD  = (const float*)d_in[8];
    const float* muE = (const float*)d_in[9];
    const float* sgE = (const float*)d_in[10];
    const float* bE  = (const float*)d_in[11];
    const float* W1  = (const float*)d_in[12];
    const float* b1  = (const float*)d_in[13];
    const float* W2  = (const float*)d_in[14];
    const float* b2  = (const float*)d_in[15];
    float* Og = (float*)d_out;

    const int smem_bytes = 2 * LUTN * (int)sizeof(float2) +
                           (D_ * QSTR + D_ * QSTR + BJ * D_ + BI * PSTR) * (int)sizeof(float);

    cudaFuncSetAttribute(attn_kernel, cudaFuncAttributeMaxDynamicSharedMemorySize, smem_bytes);

    build_luts_kernel<<<(LUTN + 255) / 256, 256>>>(muD, sgD, bD, muE, sgE, bE, W1, b1, W2, b2);

    dim3 grid(S_ / BI, H_);
    attn_kernel<<<grid, NT, smem_bytes>>>(Q, K, V, DM, EM, MK, Og);
}

// round 2
// speedup vs baseline: 1.1442x; 1.1442x over previous
#include <cuda_runtime.h>
#include <math.h>
#include <stdint.h>

// Problem constants (B=1)
#define H_   8
#define S_   1024
#define D_   64
#define KG_  10

// Tiling
#define BI   64
#define BJ   64
#define NT   256
#define NSPLIT 2
#define TILES_PER_SPLIT (S_ / BJ / NSPLIT)

// LUT
#define LUTN    2048
#define RANGE_D 10.0f
#define RANGE_E 5.0f

// smem strides (padded)
#define QSTR 68   // transposed Q/K tiles: [D][BI+4]
#define PSTR 68   // P tile: [BI][BJ+4]

__device__ float2 g_lutD[LUTN];
__device__ float2 g_lutE[LUTN];
// split-KV scratch (static __device__: no allocation)
__device__ float  g_Opart[NSPLIT][H_ * S_ * D_];
__device__ float2 g_ML[NSPLIT][H_ * S_];

// ---------------------------------------------------------------------------
// LUT construction: full RBF -> MLP(exact GELU) bias, evaluated on a grid.
// ---------------------------------------------------------------------------
__device__ __forceinline__ float gelu_exact(float x) {
    return 0.5f * x * (1.0f + erff(x * 0.70710678118654752f));
}

__device__ float bias_eval(float x,
                           const float* __restrict__ mu, const float* __restrict__ sg,
                           const float* __restrict__ bb,
                           const float* __restrict__ W1, const float* __restrict__ b1,
                           const float* __restrict__ W2, float b2v) {
    float psi[KG_];
#pragma unroll
    for (int k = 0; k < KG_; k++) {
        float s = sg[k];
        float z = (x + bb[k] - mu[k]) / s;
        psi[k] = expf(-0.5f * z * z) * (0.3989422804014327f / s);
    }
    float acc = b2v;
#pragma unroll
    for (int l = 0; l < KG_; l++) {
        float hv = b1[l];
#pragma unroll
        for (int k = 0; k < KG_; k++) hv = fmaf(W1[l * KG_ + k], psi[k], hv);
        acc = fmaf(W2[l], gelu_exact(hv), acc);
    }
    return acc;
}

__global__ void build_luts_kernel(const float* __restrict__ muD, const float* __restrict__ sgD,
                                  const float* __restrict__ bD,
                                  const float* __restrict__ muE, const float* __restrict__ sgE,
                                  const float* __restrict__ bE,
                                  const float* __restrict__ W1, const float* __restrict__ b1,
                                  const float* __restrict__ W2, const float* __restrict__ b2) {
    int i = blockIdx.x * blockDim.x + threadIdx.x;
    if (i >= LUTN) return;
    float b2v = b2[0];

    float hD = RANGE_D / (float)LUTN;
    float v0 = bias_eval((float)i * hD, muD, sgD, bD, W1, b1, W2, b2v);
    float v1 = bias_eval((float)(i + 1) * hD, muD, sgD, bD, W1, b1, W2, b2v);
    g_lutD[i] = make_float2(v0, v1 - v0);

    float hE = RANGE_E / (float)LUTN;
    v0 = bias_eval((float)i * hE, muE, sgE, bE, W1, b1, W2, b2v);
    v1 = bias_eval((float)(i + 1) * hE, muE, sgE, bE, W1, b1, W2, b2v);
    g_lutE[i] = make_float2(v0, v1 - v0);
}

// ---------------------------------------------------------------------------
// Fused flash attention with LUT biases. Split-KV partial kernel.
// grid = (S/BI, H, NSPLIT), block = 256 (16x16 thread grid, 4x4 micro-tile).
// ---------------------------------------------------------------------------
__device__ __forceinline__ float lut_interp(const float2* __restrict__ lut, float x, float scale) {
    float t = x * scale;
    int ix = (int)t;
    ix = max(0, min(ix, LUTN - 1));
    float f = t - (float)ix;
    float2 e = lut[ix];
    return fmaf(e.y, f, e.x);
}

__global__ __launch_bounds__(NT, 2) void attn_partial_kernel(
    const float* __restrict__ Qg, const float* __restrict__ Kg, const float* __restrict__ Vg,
    const float* __restrict__ DMg, const float* __restrict__ EMg, const int* __restrict__ Mg) {
    extern __shared__ unsigned char smraw[];
    float2* lutD = (float2*)smraw;
    float2* lutE = lutD + LUTN;
    float* Qs = (float*)(lutE + LUTN);   // [D][QSTR] transposed
    float* Ks = Qs + D_ * QSTR;          // [D][QSTR] transposed
    float* Vs = Ks + D_ * QSTR;          // [BJ][D]
    float* Ps = Vs + BJ * D_;            // [BI][PSTR]

    const int tid = threadIdx.x;
    const int h = blockIdx.y;
    const int i0 = blockIdx.x * BI;
    const int split = blockIdx.z;
    const int tr = tid >> 4;   // 0..15: query-row group
    const int tc = tid & 15;   // 0..15: col group

    const float lscaleD = (float)LUTN / RANGE_D;
    const float lscaleE = (float)LUTN / RANGE_E;

    // Stage LUTs into shared (coalesced)
    for (int t = tid; t < LUTN; t += NT) lutD[t] = g_lutD[t];
    for (int t = tid; t < LUTN; t += NT) lutE[t] = g_lutE[t];

    // Load Q tile transposed: Qs[d][i]
    const float* Qbase = Qg + ((size_t)h * S_ + i0) * D_;
#pragma unroll
    for (int k = 0; k < (BI * D_ / 4) / NT; k++) {
        int fi = tid + k * NT;          // 0..1023
        int row = fi >> 4;              // 16 float4 per row
        int dcol = (fi & 15) * 4;
        float4 q = *(const float4*)(Qbase + row * D_ + dcol);
        Qs[(dcol + 0) * QSTR + row] = q.x;
        Qs[(dcol + 1) * QSTR + row] = q.y;
        Qs[(dcol + 2) * QSTR + row] = q.z;
        Qs[(dcol + 3) * QSTR + row] = q.w;
    }

    float o[4][4];
    float mrow[4], lrow[4];
#pragma unroll
    for (int r = 0; r < 4; r++) {
        mrow[r] = -1e30f;
        lrow[r] = 0.f;
#pragma unroll
        for (int c = 0; c < 4; c++) o[r][c] = 0.f;
    }

    const float qk_scale = 0.0883883476483184f;  // 1/sqrt(2*D)

    for (int jt = 0; jt < TILES_PER_SPLIT; jt++) {
        const int j0 = (split * TILES_PER_SPLIT + jt) * BJ;
        __syncthreads();  // prev-iter P/K/V consumers done

        // Load K tile transposed: Ks[d][j]
        const float* Kbase = Kg + ((size_t)h * S_ + j0) * D_;
#pragma unroll
        for (int k = 0; k < 4; k++) {
            int fi = tid + k * NT;
            int row = fi >> 4;
            int dcol = (fi & 15) * 4;
            float4 v = *(const float4*)(Kbase + row * D_ + dcol);
            Ks[(dcol + 0) * QSTR + row] = v.x;
            Ks[(dcol + 1) * QSTR + row] = v.y;
            Ks[(dcol + 2) * QSTR + row] = v.z;
            Ks[(dcol + 3) * QSTR + row] = v.w;
        }
        // Load V tile straight: Vs[j][d]
        const float* Vbase = Vg + ((size_t)h * S_ + j0) * D_;
#pragma unroll
        for (int k = 0; k < 4; k++) {
            int fi = tid + k * NT;
            *(float4*)(Vs + fi * 4) = *(const float4*)(Vbase + fi * 4);
        }

        // Issue global loads for bias matrices + mask (latency hidden under QK)
        float4 dm[4], em[4];
        int4 mk[4];
#pragma unroll
        for (int r = 0; r < 4; r++) {
            int ig = i0 + tr * 4 + r;
            size_t base = ((size_t)h * S_ + ig) * S_ + j0 + tc * 4;
            dm[r] = *(const float4*)(DMg + base);
            em[r] = *(const float4*)(EMg + base);
            mk[r] = *(const int4*)(Mg + base);
        }

        __syncthreads();  // tiles visible

        // QK^T: 4x4 micro-tile per thread
        float sc[4][4];
#pragma unroll
        for (int r = 0; r < 4; r++)
#pragma unroll
            for (int c = 0; c < 4; c++) sc[r][c] = 0.f;

#pragma unroll 8
        for (int k = 0; k < D_; k++) {
            float4 a = *(const float4*)(Qs + k * QSTR + tr * 4);
            float4 b = *(const float4*)(Ks + k * QSTR + tc * 4);
            float av[4] = {a.x, a.y, a.z, a.w};
            float bv[4] = {b.x, b.y, b.z, b.w};
#pragma unroll
            for (int r = 0; r < 4; r++)
#pragma unroll
                for (int c = 0; c < 4; c++) sc[r][c] = fmaf(av[r], bv[c], sc[r][c]);
        }

        // scale + LUT biases + mask
#pragma unroll
        for (int r = 0; r < 4; r++) {
            const float* dp = (const float*)&dm[r];
            const float* ep = (const float*)&em[r];
            const int* mp = (const int*)&mk[r];
#pragma unroll
            for (int c = 0; c < 4; c++) {
                float s = sc[r][c] * qk_scale
                        + lut_interp(lutD, dp[c], lscaleD)
                        + lut_interp(lutE, ep[c], lscaleE);
                sc[r][c] = (mp[c] == 0) ? -1e9f : s;
            }
        }

        // Online softmax over this tile (row reduce across 16 lanes)
#pragma unroll
        for (int r = 0; r < 4; r++) {
            float mx = fmaxf(fmaxf(sc[r][0], sc[r][1]), fmaxf(sc[r][2], sc[r][3]));
            mx = fmaxf(mx, __shfl_xor_sync(0xffffffffu, mx, 8));
            mx = fmaxf(mx, __shfl_xor_sync(0xffffffffu, mx, 4));
            mx = fmaxf(mx, __shfl_xor_sync(0xffffffffu, mx, 2));
            mx = fmaxf(mx, __shfl_xor_sync(0xffffffffu, mx, 1));
            float mnew = fmaxf(mrow[r], mx);
            float corr = __expf(mrow[r] - mnew);
            mrow[r] = mnew;
            float ps = 0.f;
#pragma unroll
            for (int c = 0; c < 4; c++) {
                float p = __expf(sc[r][c] - mnew);
                sc[r][c] = p;
                ps += p;
            }
            ps += __shfl_xor_sync(0xffffffffu, ps, 8);
            ps += __shfl_xor_sync(0xffffffffu, ps, 4);
            ps += __shfl_xor_sync(0xffffffffu, ps, 2);
            ps += __shfl_xor_sync(0xffffffffu, ps, 1);
            lrow[r] = lrow[r] * corr + ps;
#pragma unroll
            for (int c = 0; c < 4; c++) o[r][c] *= corr;
            // Stage P tile (float4, padded stride)
            *(float4*)(Ps + (tr * 4 + r) * PSTR + tc * 4) =
                make_float4(sc[r][0], sc[r][1], sc[r][2], sc[r][3]);
        }

        __syncthreads();  // P + V visible

        // O += P * V  (vectorized P reads: 8 LDS.128 per 4 j-steps)
#pragma unroll 4
        for (int j = 0; j < BJ; j += 4) {
            float4 pr[4];
#pragma unroll
            for (int r = 0; r < 4; r++)
                pr[r] = *(const float4*)(Ps + (tr * 4 + r) * PSTR + j);
#pragma unroll
            for (int jj = 0; jj < 4; jj++) {
                float4 v = *(const float4*)(Vs + (j + jj) * D_ + tc * 4);
                float vv[4] = {v.x, v.y, v.z, v.w};
#pragma unroll
                for (int r = 0; r < 4; r++) {
                    float p = ((const float*)&pr[r])[jj];
#pragma unroll
                    for (int c = 0; c < 4; c++) o[r][c] = fmaf(p, vv[c], o[r][c]);
                }
            }
        }
    }

    // Epilogue: store un-normalized partial O + (m, l)
    float* Op = g_Opart[split];
#pragma unroll
    for (int r = 0; r < 4; r++) {
        int ig = i0 + tr * 4 + r;
        float4 res = make_float4(o[r][0], o[r][1], o[r][2], o[r][3]);
        *(float4*)(Op + ((size_t)h * S_ + ig) * D_ + tc * 4) = res;
        if (tc == 0) g_ML[split][h * S_ + ig] = make_float2(mrow[r], lrow[r]);
    }
}

// ---------------------------------------------------------------------------
// Combine pass: merge NSPLIT partial softmax results.
// ---------------------------------------------------------------------------
__global__ __launch_bounds__(256) void combine_kernel(float* __restrict__ Og) {
    int idx = blockIdx.x * blockDim.x + threadIdx.x;  // over H_*S_*(D_/4)
    if (idx >= H_ * S_ * (D_ / 4)) return;
    int row = idx >> 4;          // D_/4 == 16
    int dcol = (idx & 15) * 4;

    float2 ml0 = g_ML[0][row];
    float2 ml1 = g_ML[1][row];
    float m = fmaxf(ml0.x, ml1.x);
    float a0 = __expf(ml0.x - m);
    float a1 = __expf(ml1.x - m);
    float inv = 1.0f / fmaf(ml0.y, a0, ml1.y * a1);

    float4 o0 = *(const float4*)&g_Opart[0][(size_t)row * D_ + dcol];
    float4 o1 = *(const float4*)&g_Opart[1][(size_t)row * D_ + dcol];
    float4 r;
    r.x = fmaf(o0.x, a0, o1.x * a1) * inv;
    r.y = fmaf(o0.y, a0, o1.y * a1) * inv;
    r.z = fmaf(o0.z, a0, o1.z * a1) * inv;
    r.w = fmaf(o0.w, a0, o1.w * a1) * inv;
    *(float4*)(Og + (size_t)row * D_ + dcol) = r;
}

// ---------------------------------------------------------------------------
// kernel_launch
// Input order: Q, K, V, distance_matrix, energy_matrix, mask,
//              mu_D, sigma_D, b_D, mu_E, sigma_E, b_E, W1, b1, W2, b2
// ---------------------------------------------------------------------------
extern "C" void kernel_launch(void* const* d_in, const int* in_sizes, int n_in,
                              void* d_out, int out_size) {
    const float* Q  = (const float*)d_in[0];
    const float* K  = (const float*)d_in[1];
    const float* V  = (const float*)d_in[2];
    const float* DM = (const float*)d_in[3];
    const float* EM = (const float*)d_in[4];
    const int*   MK = (const int*)d_in[5];
    const float* muD = (const float*)d_in[6];
    const float* sgD = (const float*)d_in[7];
    const float* bD  = (const float*)d_in[8];
    const float* muE = (const float*)d_in[9];
    const float* sgE = (const float*)d_in[10];
    const float* bE  = (const float*)d_in[11];
    const float* W1  = (const float*)d_in[12];
    const float* b1  = (const float*)d_in[13];
    const float* W2  = (const float*)d_in[14];
    const float* b2  = (const float*)d_in[15];
    float* Og = (float*)d_out;

    const int smem_bytes = 2 * LUTN * (int)sizeof(float2) +
                           (D_ * QSTR + D_ * QSTR + BJ * D_ + BI * PSTR) * (int)sizeof(float);

    cudaFuncSetAttribute(attn_partial_kernel, cudaFuncAttributeMaxDynamicSharedMemorySize, smem_bytes);

    build_luts_kernel<<<(LUTN + 255) / 256, 256>>>(muD, sgD, bD, muE, sgE, bE, W1, b1, W2, b2);

    dim3 grid(S_ / BI, H_, NSPLIT);
    attn_partial_kernel<<<grid, NT, smem_bytes>>>(Q, K, V, DM, EM, MK);

    int nc = H_ * S_ * (D_ / 4);
    combine_kernel<<<(nc + 255) / 256, 256>>>(Og);
}